// round 13
// baseline (speedup 1.0000x reference)
#include <cuda_runtime.h>
#include <math.h>

#define N_NODES 100000
#define N_EDGES 1600000
#define F_IN    128
#define E_DIM   16
#define HID     64
#define G_NUM   64
#define OUT_DIM 10
#define MAXDEG  64

// ---------------- scratch (device globals; no allocations allowed) ----------------
__device__ __align__(16) float g_xtrans[N_NODES * HID];   // 25.6 MB
__device__ __align__(16) float g_skip[N_NODES * HID];     // 25.6 MB
__device__ float  g_ax[N_NODES];
__device__ __align__(16) float g_acc[N_NODES * 128];      // [wx(64) | wh(64)] per node
__device__ float  g_den[N_NODES];
__device__ int    g_cnt_e[N_NODES];                       // edges per dst
__device__ __align__(16) int g_bucket[(size_t)N_NODES * MAXDEG];  // eid per dst slot (25.6 MB)
__device__ __align__(16) float g_wt[128 * 128];           // [k][c] c<64: W_lin, c>=64: W_skip
__device__ __align__(16) float2 g_we1t2[16 * 32];         // [k][lane] = (W_e1[2l][k], W_e1[2l+1][k])
__device__ __align__(16) float g_u[64];                   // W_e2^T . att
__device__ __align__(16) float g_hloop[64];               // relu(b_e1)
__device__ __align__(16) float g_be1_raw[64];             // raw b_e1
__device__ float  g_cscal[1];                             // b_e2 . att
__device__ float  g_aloop[1];                             // hloop.u + c
__device__ float  g_sums[G_NUM * HID];
__device__ float  g_cnt[G_NUM];

// ---------------- f32x2 helpers ----------------------------------------------------
__device__ __forceinline__ unsigned long long pack2(float x, float y) {
    unsigned long long r;
    asm("mov.b64 %0, {%1, %2};" : "=l"(r) : "f"(x), "f"(y));
    return r;
}
__device__ __forceinline__ void unpack2(unsigned long long v, float& x, float& y) {
    asm("mov.b64 {%0, %1}, %2;" : "=f"(x), "=f"(y) : "l"(v));
}
__device__ __forceinline__ unsigned long long fma2(unsigned long long a, unsigned long long b,
                                                   unsigned long long c) {
    unsigned long long d;
    asm("fma.rn.f32x2 %0, %1, %2, %3;" : "=l"(d) : "l"(a), "l"(b), "l"(c));
    return d;
}
__device__ __forceinline__ unsigned long long add2(unsigned long long a, unsigned long long b) {
    unsigned long long d;
    asm("add.rn.f32x2 %0, %1, %2;" : "=l"(d) : "l"(a), "l"(b));
    return d;
}
__device__ __forceinline__ float getc(float4 v, int k) {
    return k == 0 ? v.x : (k == 1 ? v.y : (k == 2 ? v.z : v.w));
}

// ---------------- K_pre ------------------------------------------------------------
__global__ void kpre(const float* __restrict__ Wlin, const float* __restrict__ Wskip,
                     const float* __restrict__ We1,  const float* __restrict__ be1,
                     const float* __restrict__ We2,  const float* __restrict__ be2,
                     const float* __restrict__ att) {
    int t = threadIdx.x;  // 256 threads, 1 block
    for (int i = t; i < 128 * 128; i += 256) {
        int k = i >> 7, c = i & 127;
        g_wt[i] = (c < 64) ? Wlin[c * 128 + k] : Wskip[(c - 64) * 128 + k];
    }
    for (int i = t; i < 16 * 32; i += 256) {
        int k = i >> 5, l = i & 31;
        g_we1t2[i] = make_float2(We1[(2 * l) * 16 + k], We1[(2 * l + 1) * 16 + k]);
    }
    if (t < 64) {
        float uu = 0.f;
        for (int d = 0; d < 64; d++) uu += We2[d * 64 + t] * att[d];
        g_u[t] = uu;
        g_hloop[t] = fmaxf(be1[t], 0.f);
        g_be1_raw[t] = be1[t];
    }
    __syncthreads();
    if (t == 0) {
        float cc = 0.f;
        for (int d = 0; d < 64; d++) cc += be2[d] * att[d];
        g_cscal[0] = cc;
        float al = cc;
        for (int h = 0; h < 64; h++) al += g_hloop[h] * g_u[h];
        g_aloop[0] = al;
    }
}

// ---------------- K_node: [N,128] @ [128,128] -> x_trans | skip, plus a_x ---------
__global__ __launch_bounds__(256) void k_node(const float* __restrict__ x,
                                              const float* __restrict__ att) {
    __shared__ __align__(16) float xs[64 * 64];
    __shared__ __align__(16) float wsm[64 * 128];
    int t = threadIdx.x, lane = t & 31, w = t >> 5;
    int nodeBase = blockIdx.x * 64;

    unsigned long long acc[8][2];
#pragma unroll
    for (int n = 0; n < 8; n++) { acc[n][0] = pack2(0.f, 0.f); acc[n][1] = pack2(0.f, 0.f); }

    for (int kb = 0; kb < 128; kb += 64) {
#pragma unroll
        for (int j = 0; j < 4; j++) {
            int i4 = t + j * 256;
            int nl = i4 >> 4, kk4 = i4 & 15;
            int node = nodeBase + nl;
            float4 v = make_float4(0.f, 0.f, 0.f, 0.f);
            if (node < N_NODES) v = __ldg((const float4*)x + node * 32 + (kb >> 2) + kk4);
            ((float4*)xs)[nl * 16 + kk4] = v;
        }
#pragma unroll
        for (int j = 0; j < 8; j++) {
            int i4 = t + j * 256;
            ((float4*)wsm)[i4] = ((const float4*)g_wt)[((kb + (i4 >> 5)) << 5) + (i4 & 31)];
        }
        __syncthreads();
#pragma unroll 8
        for (int k = 0; k < 64; k++) {
            ulonglong2 wv = ((const ulonglong2*)wsm)[k * 32 + lane];
#pragma unroll
            for (int n = 0; n < 8; n++) {
                float xv = xs[(w * 8 + n) * 64 + k];
                unsigned long long xb = pack2(xv, xv);
                acc[n][0] = fma2(xb, wv.x, acc[n][0]);
                acc[n][1] = fma2(xb, wv.y, acc[n][1]);
            }
        }
        __syncthreads();
    }

    float4 av = make_float4(0.f, 0.f, 0.f, 0.f);
    if (lane < 16) av = __ldg((const float4*)att + lane);
#pragma unroll
    for (int n = 0; n < 8; n++) {
        int node = nodeBase + w * 8 + n;
        float o0, o1, o2, o3;
        unpack2(acc[n][0], o0, o1);
        unpack2(acc[n][1], o2, o3);
        float part = o0 * av.x + o1 * av.y + o2 * av.z + o3 * av.w;
#pragma unroll
        for (int off = 16; off; off >>= 1) part += __shfl_xor_sync(0xffffffffu, part, off);
        if (node < N_NODES) {
            float4 v = make_float4(o0, o1, o2, o3);
            if (lane < 16) ((float4*)g_xtrans)[node * 16 + lane] = v;
            else           ((float4*)g_skip)[node * 16 + (lane - 16)] = v;
            if (lane == 0) g_ax[node] = part;
        }
    }
}

// ---------------- K_bucket: thread per edge, direct capped bucketing --------------
__global__ __launch_bounds__(256) void k_bucket(const int* __restrict__ ei) {
    int e = blockIdx.x * 256 + threadIdx.x;
    if (e >= N_EDGES) return;
    int dst = __ldg(ei + N_EDGES + e);
    int pos = atomicAdd(&g_cnt_e[dst], 1);
    if (pos < MAXDEG) g_bucket[(size_t)dst * MAXDEG + pos] = e;
}

// ---------------- K_gather: half-warp per edge (lane owns 4 dims) -----------------
__global__ __launch_bounds__(256, 3) void k_gather(const int* __restrict__ ei,
                                                   const float* __restrict__ ea) {
    __shared__ __align__(16) float4 wq[16 * 16];   // [k][j] W_e1 dims 4j..4j+3, 4KB
    __shared__ __align__(16) float4 bq[16];        // b_e1 dims 4j..4j+3
    __shared__ __align__(16) float4 uq[16];        // u dims 4j..4j+3

    int t = threadIdx.x, lane = t & 31, w = t >> 5;
    int half = lane >> 4, j = lane & 15;

    {   // build weight tiles: one entry per thread
        int k = t >> 4, jj = t & 15;
        float2 p0 = g_we1t2[k * 32 + 2 * jj];
        float2 p1 = g_we1t2[k * 32 + 2 * jj + 1];
        wq[t] = make_float4(p0.x, p0.y, p1.x, p1.y);
        if (t < 16) {
            bq[t] = *((const float4*)g_be1_raw + t);
            uq[t] = *((const float4*)g_u + t);
        }
    }
    __syncthreads();

    int i = blockIdx.x * 8 + w;
    if (i >= N_NODES) return;

    float4 bv = bq[j];
    float4 uv = uq[j];
    float cconst = g_cscal[0];

    int n = min(g_cnt_e[i], MAXDEG);
    const int* row = g_bucket + (size_t)i * MAXDEG;

    unsigned long long wx01 = pack2(0.f, 0.f), wx23 = pack2(0.f, 0.f);
    unsigned long long wh01 = pack2(0.f, 0.f), wh23 = pack2(0.f, 0.f);
    float sw = 0.f;

    if (n > 0) {
        int m = n - 1;
        // prefetch pair 0: this half's edge id + src
        int e = __ldg(row + min(half, m));
        int s = __ldg(ei + e);

        for (int jj = 0; jj < n; jj += 2) {
            int ce = e, cs = s;
            // prefetch next pair's ids (2-deep chain off critical path)
            e = __ldg(row + min(jj + 2 + half, m));
            s = __ldg(ei + e);

            // inline loads for current edge (consumed late)
            float ax = __ldg(&g_ax[cs]);
            float4 xv = __ldg((const float4*)g_xtrans + (size_t)cs * 16 + j);

            const float4* q = (const float4*)ea + (size_t)ce * 4;
            float4 E0 = __ldg(q), E1 = __ldg(q + 1), E2 = __ldg(q + 2), E3 = __ldg(q + 3);

            unsigned long long h01 = pack2(bv.x, bv.y), h23 = pack2(bv.z, bv.w);
#pragma unroll
            for (int k = 0; k < 4; k++) {
                float4 wk = wq[k * 16 + j];
                float a = getc(E0, k);
                unsigned long long ap = pack2(a, a);
                h01 = fma2(ap, pack2(wk.x, wk.y), h01);
                h23 = fma2(ap, pack2(wk.z, wk.w), h23);
            }
#pragma unroll
            for (int k = 0; k < 4; k++) {
                float4 wk = wq[(4 + k) * 16 + j];
                float a = getc(E1, k);
                unsigned long long ap = pack2(a, a);
                h01 = fma2(ap, pack2(wk.x, wk.y), h01);
                h23 = fma2(ap, pack2(wk.z, wk.w), h23);
            }
#pragma unroll
            for (int k = 0; k < 4; k++) {
                float4 wk = wq[(8 + k) * 16 + j];
                float a = getc(E2, k);
                unsigned long long ap = pack2(a, a);
                h01 = fma2(ap, pack2(wk.x, wk.y), h01);
                h23 = fma2(ap, pack2(wk.z, wk.w), h23);
            }
#pragma unroll
            for (int k = 0; k < 4; k++) {
                float4 wk = wq[(12 + k) * 16 + j];
                float a = getc(E3, k);
                unsigned long long ap = pack2(a, a);
                h01 = fma2(ap, pack2(wk.x, wk.y), h01);
                h23 = fma2(ap, pack2(wk.z, wk.w), h23);
            }

            float h0, h1, h2, h3;
            unpack2(h01, h0, h1);
            unpack2(h23, h2, h3);
            h0 = fmaxf(h0, 0.f); h1 = fmaxf(h1, 0.f);
            h2 = fmaxf(h2, 0.f); h3 = fmaxf(h3, 0.f);

            // per-half score reduction: 4-step butterfly within 16 lanes
            float pr = h0 * uv.x + h1 * uv.y + h2 * uv.z + h3 * uv.w;
#pragma unroll
            for (int off = 8; off; off >>= 1) pr += __shfl_xor_sync(0xffffffffu, pr, off);

            float al = ax + pr + cconst;
            al = al > 0.f ? al : 0.2f * al;
            float wgt = (jj + half < n) ? __expf(al) : 0.f;

            unsigned long long wp = pack2(wgt, wgt);
            wx01 = fma2(wp, pack2(xv.x, xv.y), wx01);
            wx23 = fma2(wp, pack2(xv.z, xv.w), wx23);
            wh01 = fma2(wp, pack2(h0, h1), wh01);
            wh23 = fma2(wp, pack2(h2, h3), wh23);
            sw += wgt;
        }
    }

    // combine halves (edge-A sums in lanes 0-15, edge-B sums in 16-31)
    float a0, a1, a2, a3, b0, b1, b2, b3;
    unpack2(wx01, a0, a1); unpack2(wx23, a2, a3);
    unpack2(wh01, b0, b1); unpack2(wh23, b2, b3);
    a0 += __shfl_xor_sync(0xffffffffu, a0, 16);
    a1 += __shfl_xor_sync(0xffffffffu, a1, 16);
    a2 += __shfl_xor_sync(0xffffffffu, a2, 16);
    a3 += __shfl_xor_sync(0xffffffffu, a3, 16);
    b0 += __shfl_xor_sync(0xffffffffu, b0, 16);
    b1 += __shfl_xor_sync(0xffffffffu, b1, 16);
    b2 += __shfl_xor_sync(0xffffffffu, b2, 16);
    b3 += __shfl_xor_sync(0xffffffffu, b3, 16);
    sw += __shfl_xor_sync(0xffffffffu, sw, 16);

    if (half == 0) {
        ((float4*)g_acc)[(size_t)i * 32 + j] = make_float4(a0, a1, a2, a3);
        ((float4*)g_acc)[(size_t)i * 32 + 16 + j] = make_float4(b0, b1, b2, b3);
        if (lane == 0) g_den[i] = sw;
    }
}

// ---------------- K_final: tiled GEMM + normalize + skip + block-pooled sums ------
__global__ __launch_bounds__(256) void k_final(const float* __restrict__ We2,
                                               const float* __restrict__ be2,
                                               const int* __restrict__ batch,
                                               float* __restrict__ out) {
    __shared__ __align__(16) unsigned long long ws2[64 * 32];  // 16KB, [h][lane]
    __shared__ __align__(16) float hs[64 * 64];                // 16KB h tile / partials
    __shared__ __align__(16) float hl4s[64];
    __shared__ float wi_s[64], den_s[64];
    __shared__ int gb_s[64];
    __shared__ int s_cnt[8];

    int t = threadIdx.x, lane = t & 31, w = t >> 5;
    int base = blockIdx.x * 64;

#pragma unroll
    for (int j = 0; j < 8; j++) {
        int idx = t + j * 256;
        int h = idx >> 5, l = idx & 31;
        ws2[idx] = pack2(__ldg(&We2[(2 * l) * 64 + h]), __ldg(&We2[(2 * l + 1) * 64 + h]));
    }
    if (t < 64) {
        hl4s[t] = g_hloop[t];
        int i = base + t;
        if (i < N_NODES) {
            float al = g_ax[i] + g_aloop[0];
            al = al > 0.f ? al : 0.2f * al;
            float wi = __expf(al);
            wi_s[t] = wi;
            den_s[t] = g_den[i] + wi;
            gb_s[t] = __ldg(&batch[i]);
        } else {
            wi_s[t] = 0.f; den_s[t] = 1.f; gb_s[t] = -1;
        }
    }
    __syncthreads();

#pragma unroll
    for (int j = 0; j < 4; j++) {
        int idx = t + j * 256;
        int nl = idx >> 4, q = idx & 15;
        int i = base + nl;
        float4 a = make_float4(0.f, 0.f, 0.f, 0.f);
        if (i < N_NODES) a = *(const float4*)&g_acc[(size_t)i * 128 + 64 + q * 4];
        float wi = wi_s[nl];
        float4 hv = *(const float4*)&hl4s[q * 4];
        a.x += wi * hv.x; a.y += wi * hv.y; a.z += wi * hv.z; a.w += wi * hv.w;
        *(float4*)&hs[nl * 64 + q * 4] = a;
    }
    __syncthreads();

    unsigned long long acc[8];
#pragma unroll
    for (int n = 0; n < 8; n++) acc[n] = pack2(0.f, 0.f);
#pragma unroll 8
    for (int k = 0; k < 64; k++) {
        unsigned long long wv = ws2[k * 32 + lane];
#pragma unroll
        for (int n = 0; n < 8; n++) {
            float hvv = hs[(w * 8 + n) * 64 + k];
            acc[n] = fma2(pack2(hvv, hvv), wv, acc[n]);
        }
    }

    float2 be2v = __ldg((const float2*)be2 + lane);
    float xo0[8], xo1[8];
    int gb[8];
#pragma unroll
    for (int n = 0; n < 8; n++) {
        int nl = w * 8 + n;
        int i = base + nl;
        gb[n] = gb_s[nl];
        if (i < N_NODES) {
            float wi = wi_s[nl], den = den_s[nl];
            float2 ac = *(const float2*)&g_acc[(size_t)i * 128 + 2 * lane];
            float2 xt = *(const float2*)&g_xtrans[(size_t)i * 64 + 2 * lane];
            float2 sk = *(const float2*)&g_skip[(size_t)i * 64 + 2 * lane];
            float o0, o1;
            unpack2(acc[n], o0, o1);
            o0 = ac.x + wi * xt.x + o0 + den * be2v.x;
            o1 = ac.y + wi * xt.y + o1 + den * be2v.y;
            float inv = 1.f / (den + 1e-16f);
            xo0[n] = o0 * inv + sk.x;
            xo1[n] = o1 * inv + sk.y;
            *(float2*)&out[(size_t)i * 64 + 2 * lane] = make_float2(xo0[n], xo1[n]);
        } else {
            xo0[n] = 0.f; xo1[n] = 0.f;
        }
    }
    __syncthreads();  // done with hs tile; reuse as per-warp partials [8][64]

    int lastValid = min(base + 63, N_NODES - 1) - base;
    int g_lo = gb_s[0], g_hi = gb_s[lastValid];
    for (int g = g_lo; g <= g_hi; g++) {
        float p0 = 0.f, p1 = 0.f;
        int c = 0;
#pragma unroll
        for (int n = 0; n < 8; n++) {
            if (gb[n] == g) { p0 += xo0[n]; p1 += xo1[n]; c++; }
        }
        hs[w * 64 + 2 * lane] = p0;
        hs[w * 64 + 2 * lane + 1] = p1;
        if (lane == 0) s_cnt[w] = c;
        __syncthreads();
        if (t < 64) {
            float v = 0.f;
#pragma unroll
            for (int ww = 0; ww < 8; ww++) v += hs[ww * 64 + t];
            atomicAdd(&g_sums[g * 64 + t], v);
        }
        if (t == 64) {
            int v = 0;
#pragma unroll
            for (int ww = 0; ww < 8; ww++) v += s_cnt[ww];
            atomicAdd(&g_cnt[g], (float)v);
        }
        __syncthreads();
    }
}

// ---------------- K_cls ------------------------------------------------------------
__global__ void k_cls(const float* __restrict__ Wc1, const float* __restrict__ bc1,
                      const float* __restrict__ Wc2, const float* __restrict__ bc2,
                      float* __restrict__ out) {
    __shared__ float reps[4096];
    __shared__ float hid[4096];
    int t = threadIdx.x;  // 256
    for (int i = t; i < 4096; i += 256) {
        int g = i >> 6;
        float cnt = fmaxf(g_cnt[g], 1.f);
        float r = g_sums[i] / cnt;
        reps[i] = r;
        out[N_NODES * 64 + i] = r;
    }
    __syncthreads();
    for (int i = t; i < 4096; i += 256) {
        int g = i >> 6, d = i & 63;
        float s = __ldg(&bc1[d]);
        for (int h = 0; h < 64; h++) s += reps[g * 64 + h] * __ldg(&Wc1[d * 64 + h]);
        hid[i] = fmaxf(s, 0.f);
    }
    __syncthreads();
    for (int i = t; i < 640; i += 256) {
        int g = i / 10, o = i % 10;
        float s = __ldg(&bc2[o]);
        for (int h = 0; h < 64; h++) s += hid[g * 64 + h] * __ldg(&Wc2[o * 64 + h]);
        out[N_NODES * 64 + 4096 + i] = s;
    }
}

// ---------------- launch -----------------------------------------------------------
extern "C" void kernel_launch(void* const* d_in, const int* in_sizes, int n_in,
                              void* d_out, int out_size) {
    const float* x     = (const float*)d_in[0];
    const int*   ei    = (const int*)d_in[1];
    const float* ea    = (const float*)d_in[2];
    const int*   batch = (const int*)d_in[3];
    const float* Wlin  = (const float*)d_in[4];
    const float* We1   = (const float*)d_in[5];
    const float* be1   = (const float*)d_in[6];
    const float* We2   = (const float*)d_in[7];
    const float* be2   = (const float*)d_in[8];
    const float* att   = (const float*)d_in[9];
    const float* Wskip = (const float*)d_in[10];
    const float* Wc1   = (const float*)d_in[11];
    const float* bc1   = (const float*)d_in[12];
    const float* Wc2   = (const float*)d_in[13];
    const float* bc2   = (const float*)d_in[14];
    float* out = (float*)d_out;

    void *pcnt_e, *psum, *pcnt;
    cudaGetSymbolAddress(&pcnt_e, g_cnt_e);
    cudaGetSymbolAddress(&psum, g_sums);
    cudaGetSymbolAddress(&pcnt, g_cnt);
    cudaMemsetAsync(pcnt_e, 0, sizeof(int) * N_NODES);
    cudaMemsetAsync(psum, 0, sizeof(float) * G_NUM * HID);
    cudaMemsetAsync(pcnt, 0, sizeof(float) * G_NUM);

    kpre<<<1, 256>>>(Wlin, Wskip, We1, be1, We2, be2, att);
    k_bucket<<<(N_EDGES + 255) / 256, 256>>>(ei);
    k_node<<<(N_NODES + 63) / 64, 256>>>(x, att);
    k_gather<<<(N_NODES + 7) / 8, 256>>>(ei, ea);
    k_final<<<(N_NODES + 63) / 64, 256>>>(We2, be2, batch, out);
    k_cls<<<1, 256>>>(Wc1, bc1, Wc2, bc2, out);
}

// round 14
// speedup vs baseline: 1.0663x; 1.0663x over previous
#include <cuda_runtime.h>
#include <math.h>

#define N_NODES 100000
#define N_EDGES 1600000
#define F_IN    128
#define E_DIM   16
#define HID     64
#define G_NUM   64
#define OUT_DIM 10
#define MAXDEG  64

// ---------------- scratch (device globals; no allocations allowed) ----------------
__device__ __align__(16) float g_xtrans[N_NODES * HID];   // 25.6 MB
__device__ __align__(16) float g_skip[N_NODES * HID];     // 25.6 MB
__device__ float  g_ax[N_NODES];
__device__ __align__(16) float g_acc[N_NODES * 128];      // [wx(64) | wh(64)] per node
__device__ float  g_den[N_NODES];
__device__ int    g_cnt_e[N_NODES];                       // edges per dst
__device__ __align__(16) int g_bucket[(size_t)N_NODES * MAXDEG];  // eid per dst slot (25.6 MB)
__device__ __align__(16) float g_wt[128 * 128];           // [k][c] c<64: W_lin, c>=64: W_skip
__device__ __align__(16) float2 g_we1t2[16 * 32];         // [k][lane] = (W_e1[2l][k], W_e1[2l+1][k])
__device__ __align__(16) float g_u[64];                   // W_e2^T . att
__device__ __align__(16) float g_hloop[64];               // relu(b_e1)
__device__ __align__(16) float g_be1_raw[64];             // raw b_e1
__device__ float  g_cscal[1];                             // b_e2 . att
__device__ float  g_aloop[1];                             // hloop.u + c
__device__ float  g_sums[G_NUM * HID];
__device__ float  g_cnt[G_NUM];
__device__ int    g_work;                                 // work-stealing cursor

// ---------------- f32x2 helpers ----------------------------------------------------
__device__ __forceinline__ unsigned long long pack2(float x, float y) {
    unsigned long long r;
    asm("mov.b64 %0, {%1, %2};" : "=l"(r) : "f"(x), "f"(y));
    return r;
}
__device__ __forceinline__ void unpack2(unsigned long long v, float& x, float& y) {
    asm("mov.b64 {%0, %1}, %2;" : "=f"(x), "=f"(y) : "l"(v));
}
__device__ __forceinline__ unsigned long long fma2(unsigned long long a, unsigned long long b,
                                                   unsigned long long c) {
    unsigned long long d;
    asm("fma.rn.f32x2 %0, %1, %2, %3;" : "=l"(d) : "l"(a), "l"(b), "l"(c));
    return d;
}
__device__ __forceinline__ unsigned long long add2(unsigned long long a, unsigned long long b) {
    unsigned long long d;
    asm("add.rn.f32x2 %0, %1, %2;" : "=l"(d) : "l"(a), "l"(b));
    return d;
}
__device__ __forceinline__ float getc(float4 v, int k) {
    return k == 0 ? v.x : (k == 1 ? v.y : (k == 2 ? v.z : v.w));
}

// ---------------- K_pre ------------------------------------------------------------
__global__ void kpre(const float* __restrict__ Wlin, const float* __restrict__ Wskip,
                     const float* __restrict__ We1,  const float* __restrict__ be1,
                     const float* __restrict__ We2,  const float* __restrict__ be2,
                     const float* __restrict__ att) {
    int t = threadIdx.x;  // 256 threads, 1 block
    for (int i = t; i < 128 * 128; i += 256) {
        int k = i >> 7, c = i & 127;
        g_wt[i] = (c < 64) ? Wlin[c * 128 + k] : Wskip[(c - 64) * 128 + k];
    }
    for (int i = t; i < 16 * 32; i += 256) {
        int k = i >> 5, l = i & 31;
        g_we1t2[i] = make_float2(We1[(2 * l) * 16 + k], We1[(2 * l + 1) * 16 + k]);
    }
    if (t < 64) {
        float uu = 0.f;
        for (int d = 0; d < 64; d++) uu += We2[d * 64 + t] * att[d];
        g_u[t] = uu;
        g_hloop[t] = fmaxf(be1[t], 0.f);
        g_be1_raw[t] = be1[t];
    }
    __syncthreads();
    if (t == 0) {
        float cc = 0.f;
        for (int d = 0; d < 64; d++) cc += be2[d] * att[d];
        g_cscal[0] = cc;
        float al = cc;
        for (int h = 0; h < 64; h++) al += g_hloop[h] * g_u[h];
        g_aloop[0] = al;
    }
}

// ---------------- K_node: [N,128] @ [128,128] -> x_trans | skip, plus a_x ---------
__global__ __launch_bounds__(256) void k_node(const float* __restrict__ x,
                                              const float* __restrict__ att) {
    __shared__ __align__(16) float xs[64 * 64];
    __shared__ __align__(16) float wsm[64 * 128];
    int t = threadIdx.x, lane = t & 31, w = t >> 5;
    int nodeBase = blockIdx.x * 64;

    unsigned long long acc[8][2];
#pragma unroll
    for (int n = 0; n < 8; n++) { acc[n][0] = pack2(0.f, 0.f); acc[n][1] = pack2(0.f, 0.f); }

    for (int kb = 0; kb < 128; kb += 64) {
#pragma unroll
        for (int j = 0; j < 4; j++) {
            int i4 = t + j * 256;
            int nl = i4 >> 4, kk4 = i4 & 15;
            int node = nodeBase + nl;
            float4 v = make_float4(0.f, 0.f, 0.f, 0.f);
            if (node < N_NODES) v = __ldg((const float4*)x + node * 32 + (kb >> 2) + kk4);
            ((float4*)xs)[nl * 16 + kk4] = v;
        }
#pragma unroll
        for (int j = 0; j < 8; j++) {
            int i4 = t + j * 256;
            ((float4*)wsm)[i4] = ((const float4*)g_wt)[((kb + (i4 >> 5)) << 5) + (i4 & 31)];
        }
        __syncthreads();
#pragma unroll 8
        for (int k = 0; k < 64; k++) {
            ulonglong2 wv = ((const ulonglong2*)wsm)[k * 32 + lane];
#pragma unroll
            for (int n = 0; n < 8; n++) {
                float xv = xs[(w * 8 + n) * 64 + k];
                unsigned long long xb = pack2(xv, xv);
                acc[n][0] = fma2(xb, wv.x, acc[n][0]);
                acc[n][1] = fma2(xb, wv.y, acc[n][1]);
            }
        }
        __syncthreads();
    }

    float4 av = make_float4(0.f, 0.f, 0.f, 0.f);
    if (lane < 16) av = __ldg((const float4*)att + lane);
#pragma unroll
    for (int n = 0; n < 8; n++) {
        int node = nodeBase + w * 8 + n;
        float o0, o1, o2, o3;
        unpack2(acc[n][0], o0, o1);
        unpack2(acc[n][1], o2, o3);
        float part = o0 * av.x + o1 * av.y + o2 * av.z + o3 * av.w;
#pragma unroll
        for (int off = 16; off; off >>= 1) part += __shfl_xor_sync(0xffffffffu, part, off);
        if (node < N_NODES) {
            float4 v = make_float4(o0, o1, o2, o3);
            if (lane < 16) ((float4*)g_xtrans)[node * 16 + lane] = v;
            else           ((float4*)g_skip)[node * 16 + (lane - 16)] = v;
            if (lane == 0) g_ax[node] = part;
        }
    }
}

// ---------------- K_bucket: thread per edge, direct capped bucketing --------------
__global__ __launch_bounds__(256) void k_bucket(const int* __restrict__ ei) {
    int e = blockIdx.x * 256 + threadIdx.x;
    if (e >= N_EDGES) return;
    int dst = __ldg(ei + N_EDGES + e);
    int pos = atomicAdd(&g_cnt_e[dst], 1);
    if (pos < MAXDEG) g_bucket[(size_t)dst * MAXDEG + pos] = e;
}

// ---------------- K_gather: work-stealing warps, 2-edge ILP, folded reduction -----
__global__ __launch_bounds__(256, 3) void k_gather(const int* __restrict__ ei,
                                                   const float* __restrict__ ea) {
    __shared__ __align__(16) float2 wsh[8 * 32];   // [k-8][lane] W_e1 pairs for k=8..15
    int t = threadIdx.x, lane = t & 31;
    int half = lane >> 4;
#pragma unroll
    for (int j = t; j < 256; j += 256) wsh[j] = g_we1t2[256 + j];
    __syncthreads();

    // k = 0..7 weights in registers
    unsigned long long w2r[8];
#pragma unroll
    for (int k = 0; k < 8; k++) {
        float2 f = g_we1t2[k * 32 + lane];
        w2r[k] = pack2(f.x, f.y);
    }
    float bx = g_be1_raw[2 * lane], by = g_be1_raw[2 * lane + 1];
    float2 uu = ((const float2*)g_u)[lane];
    float cconst = g_cscal[0];

    while (true) {
        int base;
        if (lane == 0) base = atomicAdd(&g_work, 4);
        base = __shfl_sync(0xffffffffu, base, 0);
        if (base >= N_NODES) break;
        int lim = min(base + 4, N_NODES);

        for (int i = base; i < lim; i++) {
            int n = min(g_cnt_e[i], MAXDEG);
            const int* row = g_bucket + (size_t)i * MAXDEG;

            unsigned long long wx = pack2(0.f, 0.f), wh = pack2(0.f, 0.f);
            float sw = 0.f;

            if (n > 0) {
                int m = n - 1;
                int eA = __ldg(row);
                int eB = __ldg(row + min(1, m));
                int sA = __ldg(ei + eA);
                int sB = __ldg(ei + eB);

                for (int j = 0; j < n; j += 2) {
                    bool hasB = (j + 1 < n);
                    int ceA = eA, ceB = eB, csA = sA, csB = sB;

                    eA = __ldg(row + min(j + 2, m));
                    eB = __ldg(row + min(j + 3, m));
                    sA = __ldg(ei + eA);
                    sB = __ldg(ei + eB);

                    float axA = __ldg(&g_ax[csA]);
                    float axB = __ldg(&g_ax[csB]);
                    float2 xvA = __ldg((const float2*)g_xtrans + (size_t)csA * 32 + lane);
                    float2 xvB = __ldg((const float2*)g_xtrans + (size_t)csB * 32 + lane);

                    const float4* qA = (const float4*)ea + (size_t)ceA * 4;
                    const float4* qB = (const float4*)ea + (size_t)ceB * 4;

                    unsigned long long hA = pack2(bx, by), hB = pack2(bx, by);
                    {
                        float4 A0 = __ldg(qA), A1 = __ldg(qA + 1);
                        float4 B0 = __ldg(qB), B1 = __ldg(qB + 1);
#pragma unroll
                        for (int k = 0; k < 4; k++) {
                            float a = getc(A0, k), b = getc(B0, k);
                            hA = fma2(pack2(a, a), w2r[k], hA);
                            hB = fma2(pack2(b, b), w2r[k], hB);
                        }
#pragma unroll
                        for (int k = 0; k < 4; k++) {
                            float a = getc(A1, k), b = getc(B1, k);
                            hA = fma2(pack2(a, a), w2r[4 + k], hA);
                            hB = fma2(pack2(b, b), w2r[4 + k], hB);
                        }
                    }
                    {
                        float4 A0 = __ldg(qA + 2), A1 = __ldg(qA + 3);
                        float4 B0 = __ldg(qB + 2), B1 = __ldg(qB + 3);
#pragma unroll
                        for (int k = 0; k < 4; k++) {
                            float2 wk = wsh[k * 32 + lane];
                            unsigned long long wkp = pack2(wk.x, wk.y);
                            float a = getc(A0, k), b = getc(B0, k);
                            hA = fma2(pack2(a, a), wkp, hA);
                            hB = fma2(pack2(b, b), wkp, hB);
                        }
#pragma unroll
                        for (int k = 0; k < 4; k++) {
                            float2 wk = wsh[(4 + k) * 32 + lane];
                            unsigned long long wkp = pack2(wk.x, wk.y);
                            float a = getc(A1, k), b = getc(B1, k);
                            hA = fma2(pack2(a, a), wkp, hA);
                            hB = fma2(pack2(b, b), wkp, hB);
                        }
                    }

                    float hA0, hA1, hB0, hB1;
                    unpack2(hA, hA0, hA1);
                    unpack2(hB, hB0, hB1);
                    hA0 = fmaxf(hA0, 0.f); hA1 = fmaxf(hA1, 0.f);
                    hB0 = fmaxf(hB0, 0.f); hB1 = fmaxf(hB1, 0.f);

                    // folded reduction: edge A in lower half, edge B in upper half
                    float pA = hA0 * uu.x + hA1 * uu.y;
                    float pB = hB0 * uu.x + hB1 * uu.y;
                    float zA = pA + __shfl_xor_sync(0xffffffffu, pA, 16);
                    float zB = pB + __shfl_xor_sync(0xffffffffu, pB, 16);
                    float z = half ? zB : zA;
#pragma unroll
                    for (int off = 8; off; off >>= 1) z += __shfl_xor_sync(0xffffffffu, z, off);

                    float al = (half ? axB : axA) + z + cconst;
                    al = al > 0.f ? al : 0.2f * al;
                    bool valid = (half == 0) || hasB;
                    float wgt = valid ? __expf(al) : 0.f;
                    float wgtO = __shfl_xor_sync(0xffffffffu, wgt, 16);
                    float wgtA = half ? wgtO : wgt;
                    float wgtB = half ? wgt : wgtO;

                    wx = fma2(pack2(wgtA, wgtA), pack2(xvA.x, xvA.y), wx);
                    wh = fma2(pack2(wgtA, wgtA), pack2(hA0, hA1), wh);
                    wx = fma2(pack2(wgtB, wgtB), pack2(xvB.x, xvB.y), wx);
                    wh = fma2(pack2(wgtB, wgtB), pack2(hB0, hB1), wh);
                    sw += wgtA + wgtB;
                }
            }

            float a, b;
            unpack2(wx, a, b);
            ((float2*)g_acc)[(size_t)i * 64 + lane] = make_float2(a, b);
            unpack2(wh, a, b);
            ((float2*)g_acc)[(size_t)i * 64 + 32 + lane] = make_float2(a, b);
            if (lane == 0) g_den[i] = sw;
        }
    }
}

// ---------------- K_final: tiled GEMM + normalize + skip + block-pooled sums ------
__global__ __launch_bounds__(256) void k_final(const float* __restrict__ We2,
                                               const float* __restrict__ be2,
                                               const int* __restrict__ batch,
                                               float* __restrict__ out) {
    __shared__ __align__(16) unsigned long long ws2[64 * 32];  // 16KB, [h][lane]
    __shared__ __align__(16) float hs[64 * 64];                // 16KB h tile / partials
    __shared__ __align__(16) float hl4s[64];
    __shared__ float wi_s[64], den_s[64];
    __shared__ int gb_s[64];
    __shared__ int s_cnt[8];

    int t = threadIdx.x, lane = t & 31, w = t >> 5;
    int base = blockIdx.x * 64;

#pragma unroll
    for (int j = 0; j < 8; j++) {
        int idx = t + j * 256;
        int h = idx >> 5, l = idx & 31;
        ws2[idx] = pack2(__ldg(&We2[(2 * l) * 64 + h]), __ldg(&We2[(2 * l + 1) * 64 + h]));
    }
    if (t < 64) {
        hl4s[t] = g_hloop[t];
        int i = base + t;
        if (i < N_NODES) {
            float al = g_ax[i] + g_aloop[0];
            al = al > 0.f ? al : 0.2f * al;
            float wi = __expf(al);
            wi_s[t] = wi;
            den_s[t] = g_den[i] + wi;
            gb_s[t] = __ldg(&batch[i]);
        } else {
            wi_s[t] = 0.f; den_s[t] = 1.f; gb_s[t] = -1;
        }
    }
    __syncthreads();

#pragma unroll
    for (int j = 0; j < 4; j++) {
        int idx = t + j * 256;
        int nl = idx >> 4, q = idx & 15;
        int i = base + nl;
        float4 a = make_float4(0.f, 0.f, 0.f, 0.f);
        if (i < N_NODES) a = *(const float4*)&g_acc[(size_t)i * 128 + 64 + q * 4];
        float wi = wi_s[nl];
        float4 hv = *(const float4*)&hl4s[q * 4];
        a.x += wi * hv.x; a.y += wi * hv.y; a.z += wi * hv.z; a.w += wi * hv.w;
        *(float4*)&hs[nl * 64 + q * 4] = a;
    }
    __syncthreads();

    unsigned long long acc[8];
#pragma unroll
    for (int n = 0; n < 8; n++) acc[n] = pack2(0.f, 0.f);
#pragma unroll 8
    for (int k = 0; k < 64; k++) {
        unsigned long long wv = ws2[k * 32 + lane];
#pragma unroll
        for (int n = 0; n < 8; n++) {
            float hvv = hs[(w * 8 + n) * 64 + k];
            acc[n] = fma2(pack2(hvv, hvv), wv, acc[n]);
        }
    }

    float2 be2v = __ldg((const float2*)be2 + lane);
    float xo0[8], xo1[8];
    int gb[8];
#pragma unroll
    for (int n = 0; n < 8; n++) {
        int nl = w * 8 + n;
        int i = base + nl;
        gb[n] = gb_s[nl];
        if (i < N_NODES) {
            float wi = wi_s[nl], den = den_s[nl];
            float2 ac = *(const float2*)&g_acc[(size_t)i * 128 + 2 * lane];
            float2 xt = *(const float2*)&g_xtrans[(size_t)i * 64 + 2 * lane];
            float2 sk = *(const float2*)&g_skip[(size_t)i * 64 + 2 * lane];
            float o0, o1;
            unpack2(acc[n], o0, o1);
            o0 = ac.x + wi * xt.x + o0 + den * be2v.x;
            o1 = ac.y + wi * xt.y + o1 + den * be2v.y;
            float inv = 1.f / (den + 1e-16f);
            xo0[n] = o0 * inv + sk.x;
            xo1[n] = o1 * inv + sk.y;
            *(float2*)&out[(size_t)i * 64 + 2 * lane] = make_float2(xo0[n], xo1[n]);
        } else {
            xo0[n] = 0.f; xo1[n] = 0.f;
        }
    }
    __syncthreads();  // done with hs tile; reuse as per-warp partials [8][64]

    int lastValid = min(base + 63, N_NODES - 1) - base;
    int g_lo = gb_s[0], g_hi = gb_s[lastValid];
    for (int g = g_lo; g <= g_hi; g++) {
        float p0 = 0.f, p1 = 0.f;
        int c = 0;
#pragma unroll
        for (int n = 0; n < 8; n++) {
            if (gb[n] == g) { p0 += xo0[n]; p1 += xo1[n]; c++; }
        }
        hs[w * 64 + 2 * lane] = p0;
        hs[w * 64 + 2 * lane + 1] = p1;
        if (lane == 0) s_cnt[w] = c;
        __syncthreads();
        if (t < 64) {
            float v = 0.f;
#pragma unroll
            for (int ww = 0; ww < 8; ww++) v += hs[ww * 64 + t];
            atomicAdd(&g_sums[g * 64 + t], v);
        }
        if (t == 64) {
            int v = 0;
#pragma unroll
            for (int ww = 0; ww < 8; ww++) v += s_cnt[ww];
            atomicAdd(&g_cnt[g], (float)v);
        }
        __syncthreads();
    }
}

// ---------------- K_cls ------------------------------------------------------------
__global__ void k_cls(const float* __restrict__ Wc1, const float* __restrict__ bc1,
                      const float* __restrict__ Wc2, const float* __restrict__ bc2,
                      float* __restrict__ out) {
    __shared__ float reps[4096];
    __shared__ float hid[4096];
    int t = threadIdx.x;  // 256
    for (int i = t; i < 4096; i += 256) {
        int g = i >> 6;
        float cnt = fmaxf(g_cnt[g], 1.f);
        float r = g_sums[i] / cnt;
        reps[i] = r;
        out[N_NODES * 64 + i] = r;
    }
    __syncthreads();
    for (int i = t; i < 4096; i += 256) {
        int g = i >> 6, d = i & 63;
        float s = __ldg(&bc1[d]);
        for (int h = 0; h < 64; h++) s += reps[g * 64 + h] * __ldg(&Wc1[d * 64 + h]);
        hid[i] = fmaxf(s, 0.f);
    }
    __syncthreads();
    for (int i = t; i < 640; i += 256) {
        int g = i / 10, o = i % 10;
        float s = __ldg(&bc2[o]);
        for (int h = 0; h < 64; h++) s += hid[g * 64 + h] * __ldg(&Wc2[o * 64 + h]);
        out[N_NODES * 64 + 4096 + i] = s;
    }
}

// ---------------- launch -----------------------------------------------------------
extern "C" void kernel_launch(void* const* d_in, const int* in_sizes, int n_in,
                              void* d_out, int out_size) {
    const float* x     = (const float*)d_in[0];
    const int*   ei    = (const int*)d_in[1];
    const float* ea    = (const float*)d_in[2];
    const int*   batch = (const int*)d_in[3];
    const float* Wlin  = (const float*)d_in[4];
    const float* We1   = (const float*)d_in[5];
    const float* be1   = (const float*)d_in[6];
    const float* We2   = (const float*)d_in[7];
    const float* be2   = (const float*)d_in[8];
    const float* att   = (const float*)d_in[9];
    const float* Wskip = (const float*)d_in[10];
    const float* Wc1   = (const float*)d_in[11];
    const float* bc1   = (const float*)d_in[12];
    const float* Wc2   = (const float*)d_in[13];
    const float* bc2   = (const float*)d_in[14];
    float* out = (float*)d_out;

    void *pcnt_e, *psum, *pcnt, *pwork;
    cudaGetSymbolAddress(&pcnt_e, g_cnt_e);
    cudaGetSymbolAddress(&psum, g_sums);
    cudaGetSymbolAddress(&pcnt, g_cnt);
    cudaGetSymbolAddress(&pwork, g_work);
    cudaMemsetAsync(pcnt_e, 0, sizeof(int) * N_NODES);
    cudaMemsetAsync(psum, 0, sizeof(float) * G_NUM * HID);
    cudaMemsetAsync(pcnt, 0, sizeof(float) * G_NUM);
    cudaMemsetAsync(pwork, 0, sizeof(int));

    kpre<<<1, 256>>>(Wlin, Wskip, We1, be1, We2, be2, att);
    k_bucket<<<(N_EDGES + 255) / 256, 256>>>(ei);
    k_node<<<(N_NODES + 63) / 64, 256>>>(x, att);
    k_gather<<<444, 256>>>(ei, ea);
    k_final<<<(N_NODES + 63) / 64, 256>>>(We2, be2, batch, out);
    k_cls<<<1, 256>>>(Wc1, bc1, Wc2, bc2, out);
}

// round 15
// speedup vs baseline: 1.0869x; 1.0194x over previous
#include <cuda_runtime.h>
#include <math.h>

#define N_NODES 100000
#define N_EDGES 1600000
#define F_IN    128
#define E_DIM   16
#define HID     64
#define G_NUM   64
#define OUT_DIM 10
#define MAXDEG  64

// ---------------- scratch (device globals; no allocations allowed) ----------------
__device__ __align__(16) float g_xtrans[N_NODES * HID];   // 25.6 MB
__device__ __align__(16) float g_skip[N_NODES * HID];     // 25.6 MB
__device__ float  g_ax[N_NODES];
__device__ __align__(16) float g_acc[N_NODES * 128];      // [wx(64) | wh(64)] per node
__device__ float  g_den[N_NODES];
__device__ int    g_cnt_e[N_NODES];                       // edges per dst
__device__ __align__(16) int g_bucket[(size_t)N_NODES * MAXDEG];  // eid per dst slot (25.6 MB)
__device__ __align__(16) float g_wt[128 * 128];           // [k][c] c<64: W_lin, c>=64: W_skip
__device__ __align__(16) float2 g_we1t2[16 * 32];         // [k][lane] = (W_e1[2l][k], W_e1[2l+1][k])
__device__ __align__(16) float g_u[64];                   // W_e2^T . att
__device__ __align__(16) float g_hloop[64];               // relu(b_e1)
__device__ __align__(16) float g_be1_raw[64];             // raw b_e1
__device__ float  g_cscal[1];                             // b_e2 . att
__device__ float  g_aloop[1];                             // hloop.u + c
__device__ float  g_sums[G_NUM * HID];
__device__ float  g_cnt[G_NUM];
__device__ int    g_work;                                 // work-stealing cursor

// ---------------- f32x2 helpers ----------------------------------------------------
__device__ __forceinline__ unsigned long long pack2(float x, float y) {
    unsigned long long r;
    asm("mov.b64 %0, {%1, %2};" : "=l"(r) : "f"(x), "f"(y));
    return r;
}
__device__ __forceinline__ void unpack2(unsigned long long v, float& x, float& y) {
    asm("mov.b64 {%0, %1}, %2;" : "=f"(x), "=f"(y) : "l"(v));
}
__device__ __forceinline__ unsigned long long fma2(unsigned long long a, unsigned long long b,
                                                   unsigned long long c) {
    unsigned long long d;
    asm("fma.rn.f32x2 %0, %1, %2, %3;" : "=l"(d) : "l"(a), "l"(b), "l"(c));
    return d;
}
__device__ __forceinline__ unsigned long long add2(unsigned long long a, unsigned long long b) {
    unsigned long long d;
    asm("add.rn.f32x2 %0, %1, %2;" : "=l"(d) : "l"(a), "l"(b));
    return d;
}
__device__ __forceinline__ float getc(float4 v, int k) {
    return k == 0 ? v.x : (k == 1 ? v.y : (k == 2 ? v.z : v.w));
}

// ---------------- K_pre: weight prep + ALL zeroing (replaces memsets) --------------
__global__ void kpre(const float* __restrict__ Wlin, const float* __restrict__ Wskip,
                     const float* __restrict__ We1,  const float* __restrict__ be1,
                     const float* __restrict__ We2,  const float* __restrict__ be2,
                     const float* __restrict__ att) {
    int b = blockIdx.x, t = threadIdx.x;  // grid 104, 256 threads

    // all blocks: zero a stripe of g_cnt_e
    for (int i = b * 256 + t; i < N_NODES; i += 104 * 256) g_cnt_e[i] = 0;

    if (b == 1) {
        for (int i = t; i < G_NUM * HID; i += 256) g_sums[i] = 0.f;
        if (t < G_NUM) g_cnt[t] = 0.f;
        if (t == 0) g_work = 0;
    }
    if (b != 0) return;

    for (int i = t; i < 128 * 128; i += 256) {
        int k = i >> 7, c = i & 127;
        g_wt[i] = (c < 64) ? Wlin[c * 128 + k] : Wskip[(c - 64) * 128 + k];
    }
    for (int i = t; i < 16 * 32; i += 256) {
        int k = i >> 5, l = i & 31;
        g_we1t2[i] = make_float2(We1[(2 * l) * 16 + k], We1[(2 * l + 1) * 16 + k]);
    }
    if (t < 64) {
        float uu = 0.f;
        for (int d = 0; d < 64; d++) uu += We2[d * 64 + t] * att[d];
        g_u[t] = uu;
        g_hloop[t] = fmaxf(be1[t], 0.f);
        g_be1_raw[t] = be1[t];
    }
    __syncthreads();
    if (t == 0) {
        float cc = 0.f;
        for (int d = 0; d < 64; d++) cc += be2[d] * att[d];
        g_cscal[0] = cc;
        float al = cc;
        for (int h = 0; h < 64; h++) al += g_hloop[h] * g_u[h];
        g_aloop[0] = al;
    }
}

// ---------------- K_nb: fused node GEMM + edge bucketing (interleaved blocks) -----
// blocks with b%5==0 (1563 of them): node tile (b/5)*64
// other blocks (6250): bucket slice (b - b/5 - 1)
__global__ __launch_bounds__(256) void k_nb(const float* __restrict__ x,
                                            const float* __restrict__ att,
                                            const int* __restrict__ ei) {
    __shared__ __align__(16) float xs[64 * 64];
    __shared__ __align__(16) float wsm[64 * 128];
    int b = blockIdx.x;
    int t = threadIdx.x, lane = t & 31, w = t >> 5;

    if (b % 5 != 0) {
        // ---- bucket path ----
        int bb = b - b / 5 - 1;
        int e = bb * 256 + t;
        if (e < N_EDGES) {
            int dst = __ldg(ei + N_EDGES + e);
            int pos = atomicAdd(&g_cnt_e[dst], 1);
            if (pos < MAXDEG) g_bucket[(size_t)dst * MAXDEG + pos] = e;
        }
        return;
    }

    // ---- node GEMM path ----
    int nodeBase = (b / 5) * 64;

    unsigned long long acc[8][2];
#pragma unroll
    for (int n = 0; n < 8; n++) { acc[n][0] = pack2(0.f, 0.f); acc[n][1] = pack2(0.f, 0.f); }

    for (int kb = 0; kb < 128; kb += 64) {
#pragma unroll
        for (int j = 0; j < 4; j++) {
            int i4 = t + j * 256;
            int nl = i4 >> 4, kk4 = i4 & 15;
            int node = nodeBase + nl;
            float4 v = make_float4(0.f, 0.f, 0.f, 0.f);
            if (node < N_NODES) v = __ldg((const float4*)x + node * 32 + (kb >> 2) + kk4);
            ((float4*)xs)[nl * 16 + kk4] = v;
        }
#pragma unroll
        for (int j = 0; j < 8; j++) {
            int i4 = t + j * 256;
            ((float4*)wsm)[i4] = ((const float4*)g_wt)[((kb + (i4 >> 5)) << 5) + (i4 & 31)];
        }
        __syncthreads();
#pragma unroll 8
        for (int k = 0; k < 64; k++) {
            ulonglong2 wv = ((const ulonglong2*)wsm)[k * 32 + lane];
#pragma unroll
            for (int n = 0; n < 8; n++) {
                float xv = xs[(w * 8 + n) * 64 + k];
                unsigned long long xb = pack2(xv, xv);
                acc[n][0] = fma2(xb, wv.x, acc[n][0]);
                acc[n][1] = fma2(xb, wv.y, acc[n][1]);
            }
        }
        __syncthreads();
    }

    float4 av = make_float4(0.f, 0.f, 0.f, 0.f);
    if (lane < 16) av = __ldg((const float4*)att + lane);
#pragma unroll
    for (int n = 0; n < 8; n++) {
        int node = nodeBase + w * 8 + n;
        float o0, o1, o2, o3;
        unpack2(acc[n][0], o0, o1);
        unpack2(acc[n][1], o2, o3);
        float part = o0 * av.x + o1 * av.y + o2 * av.z + o3 * av.w;
#pragma unroll
        for (int off = 16; off; off >>= 1) part += __shfl_xor_sync(0xffffffffu, part, off);
        if (node < N_NODES) {
            float4 v = make_float4(o0, o1, o2, o3);
            if (lane < 16) ((float4*)g_xtrans)[node * 16 + lane] = v;
            else           ((float4*)g_skip)[node * 16 + (lane - 16)] = v;
            if (lane == 0) g_ax[node] = part;
        }
    }
}

// ---------------- K_gather: work-stealing warps, 2-edge ILP, folded reduction -----
__global__ __launch_bounds__(256, 3) void k_gather(const int* __restrict__ ei,
                                                   const float* __restrict__ ea) {
    __shared__ __align__(16) float2 wsh[8 * 32];   // [k-8][lane] W_e1 pairs for k=8..15
    int t = threadIdx.x, lane = t & 31;
    int half = lane >> 4;
#pragma unroll
    for (int j = t; j < 256; j += 256) wsh[j] = g_we1t2[256 + j];
    __syncthreads();

    // k = 0..7 weights in registers
    unsigned long long w2r[8];
#pragma unroll
    for (int k = 0; k < 8; k++) {
        float2 f = g_we1t2[k * 32 + lane];
        w2r[k] = pack2(f.x, f.y);
    }
    float bx = g_be1_raw[2 * lane], by = g_be1_raw[2 * lane + 1];
    float2 uu = ((const float2*)g_u)[lane];
    float cconst = g_cscal[0];

    while (true) {
        int base;
        if (lane == 0) base = atomicAdd(&g_work, 4);
        base = __shfl_sync(0xffffffffu, base, 0);
        if (base >= N_NODES) break;
        int lim = min(base + 4, N_NODES);

        for (int i = base; i < lim; i++) {
            int n = min(g_cnt_e[i], MAXDEG);
            const int* row = g_bucket + (size_t)i * MAXDEG;

            unsigned long long wx = pack2(0.f, 0.f), wh = pack2(0.f, 0.f);
            float sw = 0.f;

            if (n > 0) {
                int m = n - 1;
                int eA = __ldg(row);
                int eB = __ldg(row + min(1, m));
                int sA = __ldg(ei + eA);
                int sB = __ldg(ei + eB);

                for (int j = 0; j < n; j += 2) {
                    bool hasB = (j + 1 < n);
                    int ceA = eA, ceB = eB, csA = sA, csB = sB;

                    eA = __ldg(row + min(j + 2, m));
                    eB = __ldg(row + min(j + 3, m));
                    sA = __ldg(ei + eA);
                    sB = __ldg(ei + eB);

                    float axA = __ldg(&g_ax[csA]);
                    float axB = __ldg(&g_ax[csB]);
                    float2 xvA = __ldg((const float2*)g_xtrans + (size_t)csA * 32 + lane);
                    float2 xvB = __ldg((const float2*)g_xtrans + (size_t)csB * 32 + lane);

                    const float4* qA = (const float4*)ea + (size_t)ceA * 4;
                    const float4* qB = (const float4*)ea + (size_t)ceB * 4;

                    unsigned long long hA = pack2(bx, by), hB = pack2(bx, by);
                    {
                        float4 A0 = __ldg(qA), A1 = __ldg(qA + 1);
                        float4 B0 = __ldg(qB), B1 = __ldg(qB + 1);
#pragma unroll
                        for (int k = 0; k < 4; k++) {
                            float a = getc(A0, k), b = getc(B0, k);
                            hA = fma2(pack2(a, a), w2r[k], hA);
                            hB = fma2(pack2(b, b), w2r[k], hB);
                        }
#pragma unroll
                        for (int k = 0; k < 4; k++) {
                            float a = getc(A1, k), b = getc(B1, k);
                            hA = fma2(pack2(a, a), w2r[4 + k], hA);
                            hB = fma2(pack2(b, b), w2r[4 + k], hB);
                        }
                    }
                    {
                        float4 A0 = __ldg(qA + 2), A1 = __ldg(qA + 3);
                        float4 B0 = __ldg(qB + 2), B1 = __ldg(qB + 3);
#pragma unroll
                        for (int k = 0; k < 4; k++) {
                            float2 wk = wsh[k * 32 + lane];
                            unsigned long long wkp = pack2(wk.x, wk.y);
                            float a = getc(A0, k), b = getc(B0, k);
                            hA = fma2(pack2(a, a), wkp, hA);
                            hB = fma2(pack2(b, b), wkp, hB);
                        }
#pragma unroll
                        for (int k = 0; k < 4; k++) {
                            float2 wk = wsh[(4 + k) * 32 + lane];
                            unsigned long long wkp = pack2(wk.x, wk.y);
                            float a = getc(A1, k), b = getc(B1, k);
                            hA = fma2(pack2(a, a), wkp, hA);
                            hB = fma2(pack2(b, b), wkp, hB);
                        }
                    }

                    float hA0, hA1, hB0, hB1;
                    unpack2(hA, hA0, hA1);
                    unpack2(hB, hB0, hB1);
                    hA0 = fmaxf(hA0, 0.f); hA1 = fmaxf(hA1, 0.f);
                    hB0 = fmaxf(hB0, 0.f); hB1 = fmaxf(hB1, 0.f);

                    // folded reduction: edge A in lower half, edge B in upper half
                    float pA = hA0 * uu.x + hA1 * uu.y;
                    float pB = hB0 * uu.x + hB1 * uu.y;
                    float zA = pA + __shfl_xor_sync(0xffffffffu, pA, 16);
                    float zB = pB + __shfl_xor_sync(0xffffffffu, pB, 16);
                    float z = half ? zB : zA;
#pragma unroll
                    for (int off = 8; off; off >>= 1) z += __shfl_xor_sync(0xffffffffu, z, off);

                    float al = (half ? axB : axA) + z + cconst;
                    al = al > 0.f ? al : 0.2f * al;
                    bool valid = (half == 0) || hasB;
                    float wgt = valid ? __expf(al) : 0.f;
                    float wgtO = __shfl_xor_sync(0xffffffffu, wgt, 16);
                    float wgtA = half ? wgtO : wgt;
                    float wgtB = half ? wgt : wgtO;

                    wx = fma2(pack2(wgtA, wgtA), pack2(xvA.x, xvA.y), wx);
                    wh = fma2(pack2(wgtA, wgtA), pack2(hA0, hA1), wh);
                    wx = fma2(pack2(wgtB, wgtB), pack2(xvB.x, xvB.y), wx);
                    wh = fma2(pack2(wgtB, wgtB), pack2(hB0, hB1), wh);
                    sw += wgtA + wgtB;
                }
            }

            float a, b;
            unpack2(wx, a, b);
            ((float2*)g_acc)[(size_t)i * 64 + lane] = make_float2(a, b);
            unpack2(wh, a, b);
            ((float2*)g_acc)[(size_t)i * 64 + 32 + lane] = make_float2(a, b);
            if (lane == 0) g_den[i] = sw;
        }
    }
}

// ---------------- K_final: tiled GEMM + normalize + skip + block-pooled sums ------
__global__ __launch_bounds__(256) void k_final(const float* __restrict__ We2,
                                               const float* __restrict__ be2,
                                               const int* __restrict__ batch,
                                               float* __restrict__ out) {
    __shared__ __align__(16) unsigned long long ws2[64 * 32];  // 16KB, [h][lane]
    __shared__ __align__(16) float hs[64 * 64];                // 16KB h tile / partials
    __shared__ __align__(16) float hl4s[64];
    __shared__ float wi_s[64], den_s[64];
    __shared__ int gb_s[64];
    __shared__ int s_cnt[8];

    int t = threadIdx.x, lane = t & 31, w = t >> 5;
    int base = blockIdx.x * 64;

#pragma unroll
    for (int j = 0; j < 8; j++) {
        int idx = t + j * 256;
        int h = idx >> 5, l = idx & 31;
        ws2[idx] = pack2(__ldg(&We2[(2 * l) * 64 + h]), __ldg(&We2[(2 * l + 1) * 64 + h]));
    }
    if (t < 64) {
        hl4s[t] = g_hloop[t];
        int i = base + t;
        if (i < N_NODES) {
            float al = g_ax[i] + g_aloop[0];
            al = al > 0.f ? al : 0.2f * al;
            float wi = __expf(al);
            wi_s[t] = wi;
            den_s[t] = g_den[i] + wi;
            gb_s[t] = __ldg(&batch[i]);
        } else {
            wi_s[t] = 0.f; den_s[t] = 1.f; gb_s[t] = -1;
        }
    }
    __syncthreads();

#pragma unroll
    for (int j = 0; j < 4; j++) {
        int idx = t + j * 256;
        int nl = idx >> 4, q = idx & 15;
        int i = base + nl;
        float4 a = make_float4(0.f, 0.f, 0.f, 0.f);
        if (i < N_NODES) a = *(const float4*)&g_acc[(size_t)i * 128 + 64 + q * 4];
        float wi = wi_s[nl];
        float4 hv = *(const float4*)&hl4s[q * 4];
        a.x += wi * hv.x; a.y += wi * hv.y; a.z += wi * hv.z; a.w += wi * hv.w;
        *(float4*)&hs[nl * 64 + q * 4] = a;
    }
    __syncthreads();

    unsigned long long acc[8];
#pragma unroll
    for (int n = 0; n < 8; n++) acc[n] = pack2(0.f, 0.f);
#pragma unroll 8
    for (int k = 0; k < 64; k++) {
        unsigned long long wv = ws2[k * 32 + lane];
#pragma unroll
        for (int n = 0; n < 8; n++) {
            float hvv = hs[(w * 8 + n) * 64 + k];
            acc[n] = fma2(pack2(hvv, hvv), wv, acc[n]);
        }
    }

    float2 be2v = __ldg((const float2*)be2 + lane);
    float xo0[8], xo1[8];
    int gb[8];
#pragma unroll
    for (int n = 0; n < 8; n++) {
        int nl = w * 8 + n;
        int i = base + nl;
        gb[n] = gb_s[nl];
        if (i < N_NODES) {
            float wi = wi_s[nl], den = den_s[nl];
            float2 ac = *(const float2*)&g_acc[(size_t)i * 128 + 2 * lane];
            float2 xt = *(const float2*)&g_xtrans[(size_t)i * 64 + 2 * lane];
            float2 sk = *(const float2*)&g_skip[(size_t)i * 64 + 2 * lane];
            float o0, o1;
            unpack2(acc[n], o0, o1);
            o0 = ac.x + wi * xt.x + o0 + den * be2v.x;
            o1 = ac.y + wi * xt.y + o1 + den * be2v.y;
            float inv = 1.f / (den + 1e-16f);
            xo0[n] = o0 * inv + sk.x;
            xo1[n] = o1 * inv + sk.y;
            *(float2*)&out[(size_t)i * 64 + 2 * lane] = make_float2(xo0[n], xo1[n]);
        } else {
            xo0[n] = 0.f; xo1[n] = 0.f;
        }
    }
    __syncthreads();  // done with hs tile; reuse as per-warp partials [8][64]

    int lastValid = min(base + 63, N_NODES - 1) - base;
    int g_lo = gb_s[0], g_hi = gb_s[lastValid];
    for (int g = g_lo; g <= g_hi; g++) {
        float p0 = 0.f, p1 = 0.f;
        int c = 0;
#pragma unroll
        for (int n = 0; n < 8; n++) {
            if (gb[n] == g) { p0 += xo0[n]; p1 += xo1[n]; c++; }
        }
        hs[w * 64 + 2 * lane] = p0;
        hs[w * 64 + 2 * lane + 1] = p1;
        if (lane == 0) s_cnt[w] = c;
        __syncthreads();
        if (t < 64) {
            float v = 0.f;
#pragma unroll
            for (int ww = 0; ww < 8; ww++) v += hs[ww * 64 + t];
            atomicAdd(&g_sums[g * 64 + t], v);
        }
        if (t == 64) {
            int v = 0;
#pragma unroll
            for (int ww = 0; ww < 8; ww++) v += s_cnt[ww];
            atomicAdd(&g_cnt[g], (float)v);
        }
        __syncthreads();
    }
}

// ---------------- K_cls ------------------------------------------------------------
__global__ void k_cls(const float* __restrict__ Wc1, const float* __restrict__ bc1,
                      const float* __restrict__ Wc2, const float* __restrict__ bc2,
                      float* __restrict__ out) {
    __shared__ float reps[4096];
    __shared__ float hid[4096];
    int t = threadIdx.x;  // 256
    for (int i = t; i < 4096; i += 256) {
        int g = i >> 6;
        float cnt = fmaxf(g_cnt[g], 1.f);
        float r = g_sums[i] / cnt;
        reps[i] = r;
        out[N_NODES * 64 + i] = r;
    }
    __syncthreads();
    for (int i = t; i < 4096; i += 256) {
        int g = i >> 6, d = i & 63;
        float s = __ldg(&bc1[d]);
        for (int h = 0; h < 64; h++) s += reps[g * 64 + h] * __ldg(&Wc1[d * 64 + h]);
        hid[i] = fmaxf(s, 0.f);
    }
    __syncthreads();
    for (int i = t; i < 640; i += 256) {
        int g = i / 10, o = i % 10;
        float s = __ldg(&bc2[o]);
        for (int h = 0; h < 64; h++) s += hid[g * 64 + h] * __ldg(&Wc2[o * 64 + h]);
        out[N_NODES * 64 + 4096 + i] = s;
    }
}

// ---------------- launch -----------------------------------------------------------
extern "C" void kernel_launch(void* const* d_in, const int* in_sizes, int n_in,
                              void* d_out, int out_size) {
    const float* x     = (const float*)d_in[0];
    const int*   ei    = (const int*)d_in[1];
    const float* ea    = (const float*)d_in[2];
    const int*   batch = (const int*)d_in[3];
    const float* Wlin  = (const float*)d_in[4];
    const float* We1   = (const float*)d_in[5];
    const float* be1   = (const float*)d_in[6];
    const float* We2   = (const float*)d_in[7];
    const float* be2   = (const float*)d_in[8];
    const float* att   = (const float*)d_in[9];
    const float* Wskip = (const float*)d_in[10];
    const float* Wc1   = (const float*)d_in[11];
    const float* bc1   = (const float*)d_in[12];
    const float* Wc2   = (const float*)d_in[13];
    const float* bc2   = (const float*)d_in[14];
    float* out = (float*)d_out;

    kpre<<<104, 256>>>(Wlin, Wskip, We1, be1, We2, be2, att);
    k_nb<<<7813, 256>>>(x, att, ei);           // fused node GEMM + bucketing
    k_gather<<<444, 256>>>(ei, ea);
    k_final<<<(N_NODES + 63) / 64, 256>>>(We2, be2, batch, out);
    k_cls<<<1, 256>>>(Wc1, bc1, Wc2, bc2, out);
}